// round 10
// baseline (speedup 1.0000x reference)
#include <cuda_runtime.h>
#include <cuda_bf16.h>
#include <cstdint>

// =====================================================================
// ATQCNN factorization:
//   U = fixed 128x128 orthogonal circuit matrix (wires 0..6; 7,8 inert)
//   Y[b] = U x[b];  q[b,k] = sum_{m&3==k} Y[b,m]^2;  out = softmax(q/sum q)
// Kernel 1: warp-per-basis register simulation -> U as bf16 split
//           (U = U_hi + U_lo residual; 3-pass product err ~1e-5).
// Kernel 2: mma.sync (m16n8k16 bf16) GEMM, 3 accumulated passes
//           (Xhi·Uhi + Xlo·Uhi + Xhi·Ulo), register accumulators,
//           shuffle epilogue (squared-sum + softmax). No tcgen05 —
//           harness PTX target is plain sm_103.
// =====================================================================

__device__ __align__(16) __nv_bfloat16 g_Uhi[128 * 128];  // [m][i] row-major
__device__ __align__(16) __nv_bfloat16 g_Ulo[128 * 128];  // [m][i] row-major

// --------------------- warp-MMA helpers -------------------------------
__device__ __forceinline__ uint32_t smem_to_u32(const void* p) {
    uint32_t a;
    asm("{ .reg .u64 t; cvta.to.shared.u64 t, %1; cvt.u32.u64 %0, t; }"
        : "=r"(a) : "l"(p));
    return a;
}
__device__ __forceinline__ void ldsm4(uint32_t& r0, uint32_t& r1,
                                      uint32_t& r2, uint32_t& r3, uint32_t a) {
    asm volatile("ldmatrix.sync.aligned.m8n8.x4.shared.b16 {%0,%1,%2,%3}, [%4];"
                 : "=r"(r0), "=r"(r1), "=r"(r2), "=r"(r3) : "r"(a));
}
__device__ __forceinline__ void ldsm2(uint32_t& r0, uint32_t& r1, uint32_t a) {
    asm volatile("ldmatrix.sync.aligned.m8n8.x2.shared.b16 {%0,%1}, [%2];"
                 : "=r"(r0), "=r"(r1) : "r"(a));
}
__device__ __forceinline__ void mma_bf16(float* d, const uint32_t* a,
                                         uint32_t b0, uint32_t b1) {
    asm volatile(
        "mma.sync.aligned.m16n8k16.row.col.f32.bf16.bf16.f32 "
        "{%0,%1,%2,%3}, {%4,%5,%6,%7}, {%8,%9}, {%0,%1,%2,%3};"
        : "+f"(d[0]), "+f"(d[1]), "+f"(d[2]), "+f"(d[3])
        : "r"(a[0]), "r"(a[1]), "r"(a[2]), "r"(a[3]), "r"(b0), "r"(b1));
}
__device__ __forceinline__ uint32_t pack_bf2(__nv_bfloat16 a, __nv_bfloat16 b) {
    __nv_bfloat162 t = __halves2bfloat162(a, b);
    return *reinterpret_cast<uint32_t*>(&t);
}

// --------------------- gate primitives (register sim) -----------------
template<int P>
__device__ __forceinline__ void ry_p(float a[4], float c, float s, int lane) {
    if constexpr (P == 0) {
        float n0 = c * a[0] - s * a[1];
        float n1 = fmaf(s, a[0], c * a[1]);
        float n2 = c * a[2] - s * a[3];
        float n3 = fmaf(s, a[2], c * a[3]);
        a[0] = n0; a[1] = n1; a[2] = n2; a[3] = n3;
    } else if constexpr (P == 1) {
        float n0 = c * a[0] - s * a[2];
        float n2 = fmaf(s, a[0], c * a[2]);
        float n1 = c * a[1] - s * a[3];
        float n3 = fmaf(s, a[1], c * a[3]);
        a[0] = n0; a[1] = n1; a[2] = n2; a[3] = n3;
    } else {
        constexpr int M = 1 << (P - 2);
        const float sgn = (lane & M) ? s : -s;
        #pragma unroll
        for (int r = 0; r < 4; ++r) {
            float pr = __shfl_xor_sync(0xffffffffu, a[r], M);
            a[r] = fmaf(sgn, pr, c * a[r]);
        }
    }
}
template<int W>
__device__ __forceinline__ void ry_w(float a[4], float2 cs, int lane) {
    ry_p<6 - W>(a, cs.x, cs.y, lane);
}
template<int PC, int PT>
__device__ __forceinline__ void cnot_p(float a[4], int lane) {
    if constexpr (PT >= 2) {
        constexpr int MT = 1 << (PT - 2);
        if constexpr (PC >= 2) {
            constexpr int MC = 1 << (PC - 2);
            const bool ctl = (lane & MC) != 0;
            #pragma unroll
            for (int r = 0; r < 4; ++r) {
                float pr = __shfl_xor_sync(0xffffffffu, a[r], MT);
                a[r] = ctl ? pr : a[r];
            }
        } else {
            #pragma unroll
            for (int r = 0; r < 4; ++r) {
                if ((r >> PC) & 1) {
                    a[r] = __shfl_xor_sync(0xffffffffu, a[r], MT);
                }
            }
        }
    } else {
        if constexpr (PC >= 2) {
            constexpr int MC = 1 << (PC - 2);
            const bool ctl = (lane & MC) != 0;
            if constexpr (PT == 0) {
                float t0 = a[0], t2 = a[2];
                a[0] = ctl ? a[1] : a[0];  a[1] = ctl ? t0 : a[1];
                a[2] = ctl ? a[3] : a[2];  a[3] = ctl ? t2 : a[3];
            } else {
                float t0 = a[0], t1 = a[1];
                a[0] = ctl ? a[2] : a[0];  a[2] = ctl ? t0 : a[2];
                a[1] = ctl ? a[3] : a[1];  a[3] = ctl ? t1 : a[3];
            }
        } else {
            if constexpr (PC == 1 && PT == 0) { float t = a[2]; a[2] = a[3]; a[3] = t; }
            else                              { float t = a[1]; a[1] = a[3]; a[3] = t; }
        }
    }
}
template<int C, int T>
__device__ __forceinline__ void cnot_w(float a[4], int lane) {
    cnot_p<6 - C, 6 - T>(a, lane);
}
template<int WA, int WB>
__device__ __forceinline__ void conv6(float a[4], int lane,
                                      const float2* __restrict__ cs, int base) {
    #pragma unroll
    for (int q = 0; q < 6; ++q) {
        ry_w<WA>(a, cs[base + 2 * q], lane);
        ry_w<WB>(a, cs[base + 2 * q + 1], lane);
        cnot_w<WA, WB>(a, lane);
    }
}

// ----------------------------- Kernel 1 ------------------------------
// 16 blocks x 256 threads; one warp per basis state (= input index i).
__global__ __launch_bounds__(256) void build_U_kernel(
        const float* __restrict__ QC1, const float* __restrict__ QC2,
        const float* __restrict__ QC3, const float* __restrict__ QP1,
        const float* __restrict__ QP2, const float* __restrict__ QP3,
        const float* __restrict__ QF) {
    __shared__ float2 cs[46];
    const int tid  = threadIdx.x;
    const int lane = tid & 31;
    const int basis = blockIdx.x * 8 + (tid >> 5);

    if (tid < 46) {
        float ang;
        if      (tid < 12) ang = QC1[tid];
        else if (tid < 24) ang = QC2[tid - 12];
        else if (tid < 36) ang = QC3[tid - 24];
        else if (tid == 36) ang =  QP1[0];
        else if (tid == 37) ang =  QP1[1];
        else if (tid == 38) ang = -QP1[1];
        else if (tid == 39) ang =  QP2[0];
        else if (tid == 40) ang =  QP2[1];
        else if (tid == 41) ang = -QP2[1];
        else if (tid == 42) ang =  QP3[0];
        else if (tid == 43) ang =  QP3[1];
        else if (tid == 44) ang = -QP3[1];
        else               ang = QF[0] + QF[1] + QF[2] + QF[3];  // RY angles add
        float sn, c;
        sincosf(0.5f * ang, &sn, &c);
        cs[tid] = make_float2(c, sn);
    }
    __syncthreads();

    float a[4];
    #pragma unroll
    for (int r = 0; r < 4; ++r) a[r] = (lane * 4 + r == basis) ? 1.0f : 0.0f;

    conv6<0,1>(a, lane, cs, 0);  conv6<1,2>(a, lane, cs, 0);
    conv6<2,3>(a, lane, cs, 0);  conv6<3,4>(a, lane, cs, 0);
    conv6<4,5>(a, lane, cs, 0);  conv6<5,6>(a, lane, cs, 0);
    conv6<6,0>(a, lane, cs, 0);
    ry_w<0>(a, cs[36], lane); ry_w<3>(a, cs[37], lane);
    cnot_w<0,3>(a, lane);     ry_w<3>(a, cs[38], lane);
    ry_w<1>(a, cs[36], lane); ry_w<4>(a, cs[37], lane);
    cnot_w<1,4>(a, lane);     ry_w<4>(a, cs[38], lane);
    ry_w<2>(a, cs[36], lane); ry_w<5>(a, cs[37], lane);
    cnot_w<2,5>(a, lane);     ry_w<5>(a, cs[38], lane);
    conv6<3,4>(a, lane, cs, 12);
    conv6<4,5>(a, lane, cs, 12);
    conv6<5,6>(a, lane, cs, 12);
    #pragma unroll
    for (int q = 0; q < 6; ++q) {
        ry_w<6>(a, cs[12 + 2 * q], lane);
        ry_w<3>(a, cs[13 + 2 * q], lane);
        cnot_w<6,0>(a, lane);
    }
    ry_w<3>(a, cs[39], lane); ry_w<5>(a, cs[40], lane);
    cnot_w<3,5>(a, lane);     ry_w<5>(a, cs[41], lane);
    ry_w<4>(a, cs[39], lane); ry_w<6>(a, cs[40], lane);
    cnot_w<4,6>(a, lane);     ry_w<6>(a, cs[41], lane);
    #pragma unroll
    for (int q = 0; q < 6; ++q) {
        ry_w<5>(a, cs[24 + 2 * q], lane);
        ry_w<6>(a, cs[25 + 2 * q], lane);
        cnot_w<4,5>(a, lane);
    }
    ry_w<5>(a, cs[42], lane); ry_w<6>(a, cs[43], lane);
    cnot_w<4,6>(a, lane);     ry_w<6>(a, cs[44], lane);
    ry_w<5>(a, cs[45], lane);
    cnot_w<5,6>(a, lane);
    cnot_w<6,5>(a, lane);

    // a[r] = U[m = lane*4 + r][i = basis]; split to bf16 hi + residual lo.
    #pragma unroll
    for (int r = 0; r < 4; ++r) {
        const int m = lane * 4 + r;
        const __nv_bfloat16 h = __float2bfloat16(a[r]);
        g_Uhi[m * 128 + basis] = h;
        g_Ulo[m * 128 + basis] = __float2bfloat16(a[r] - __bfloat162float(h));
    }
}

// ----------------------------- Kernel 2 ------------------------------
// 64 blocks x 128 threads (4 warps). Block = 64 batches; warp = 16 rows
// x 128 output cols = 16 m16n8 accum tiles, K = 128 = 8 k16 steps.
// A = X[b][i] row-major (ldmatrix no-trans); B = U[m][i] row-major
// (= col-major B for row.col mma; ldmatrix no-trans).
// Smem rows padded to 272 B so ldmatrix row pointers are conflict-free.

#define TCA_THREADS 128
#define TCA_ROWS 64
#define PITCH 272                                // bytes per tile row
#define SM_XHI 0
#define SM_XLO (TCA_ROWS * PITCH)
#define SM_UHI (2 * TCA_ROWS * PITCH)
#define SM_ULO (2 * TCA_ROWS * PITCH + 128 * PITCH)
#define SM_TC_TOTAL (2 * TCA_ROWS * PITCH + 2 * 128 * PITCH)  // 104448 B

__global__ __launch_bounds__(TCA_THREADS) void qcnn_mma_kernel(
        const float* __restrict__ X, float* __restrict__ out) {
    extern __shared__ char smem[];
    const uint32_t smem_base = smem_to_u32(smem);
    const int tid  = threadIdx.x;
    const int warp = tid >> 5;
    const int lane = tid & 31;

    // --- Stage X tile (64 rows) as bf16 hi/lo into padded smem ---
    const float4* gX4 =
        reinterpret_cast<const float4*>(X + (size_t)blockIdx.x * TCA_ROWS * 128);
    #pragma unroll
    for (int it = 0; it < 16; ++it) {
        const int idx = tid + it * TCA_THREADS;   // 2048 float4 chunks
        const float4 v = gX4[idx];
        const int row = idx >> 5;
        const int col = (idx & 31) << 2;
        const __nv_bfloat16 h0 = __float2bfloat16(v.x);
        const __nv_bfloat16 h1 = __float2bfloat16(v.y);
        const __nv_bfloat16 h2 = __float2bfloat16(v.z);
        const __nv_bfloat16 h3 = __float2bfloat16(v.w);
        const __nv_bfloat16 l0 = __float2bfloat16(v.x - __bfloat162float(h0));
        const __nv_bfloat16 l1 = __float2bfloat16(v.y - __bfloat162float(h1));
        const __nv_bfloat16 l2 = __float2bfloat16(v.z - __bfloat162float(h2));
        const __nv_bfloat16 l3 = __float2bfloat16(v.w - __bfloat162float(h3));
        const int off = row * PITCH + col * 2;
        *reinterpret_cast<uint2*>(smem + SM_XHI + off) =
            make_uint2(pack_bf2(h0, h1), pack_bf2(h2, h3));
        *reinterpret_cast<uint2*>(smem + SM_XLO + off) =
            make_uint2(pack_bf2(l0, l1), pack_bf2(l2, l3));
    }
    // --- Stage U hi/lo (128 rows) into padded smem ---
    const uint2* gUh = reinterpret_cast<const uint2*>(g_Uhi);  // 4 bf16/uint2
    const uint2* gUl = reinterpret_cast<const uint2*>(g_Ulo);
    #pragma unroll
    for (int it = 0; it < 32; ++it) {
        const int idx = tid + it * TCA_THREADS;   // 4096 uint2 chunks
        const int row = idx >> 5;
        const int col = (idx & 31) << 2;
        const int off = row * PITCH + col * 2;
        *reinterpret_cast<uint2*>(smem + SM_UHI + off) = gUh[idx];
        *reinterpret_cast<uint2*>(smem + SM_ULO + off) = gUl[idx];
    }
    __syncthreads();

    // --- MMA mainloop: 3 passes x 8 k-steps x 16 n-tiles ---
    float d[16][4];
    #pragma unroll
    for (int j = 0; j < 16; ++j)
        { d[j][0] = 0.f; d[j][1] = 0.f; d[j][2] = 0.f; d[j][3] = 0.f; }

    const int R0 = warp * 16;                     // warp's row base
    const uint32_t a_off[3] = {SM_XHI, SM_XLO, SM_XHI};
    const uint32_t b_off[3] = {SM_UHI, SM_UHI, SM_ULO};

    #pragma unroll 1
    for (int p = 0; p < 3; ++p) {
        const uint32_t abase = smem_base + a_off[p]
            + (uint32_t)(R0 + (lane & 15)) * PITCH + (uint32_t)(lane >> 4) * 16;
        const uint32_t bbase = smem_base + b_off[p]
            + (uint32_t)(lane & 7) * PITCH + (uint32_t)((lane >> 3) & 1) * 16;
        #pragma unroll 1
        for (int ks = 0; ks < 8; ++ks) {
            uint32_t a[4];
            ldsm4(a[0], a[1], a[2], a[3], abase + ks * 32);
            const uint32_t bks = bbase + ks * 32;
            #pragma unroll
            for (int j = 0; j < 16; ++j) {
                uint32_t b0, b1;
                ldsm2(b0, b1, bks + j * (8 * PITCH));
                mma_bf16(d[j], a, b0, b1);
            }
        }
    }

    // --- Epilogue (register fragments, shuffle reduce) ---
    // c0/c1 cols = ntile*8 + 2*(lane&3) + {0,1}; rows r=lane>>2 and r+8.
    // lane&3 in {0,2}: (c0,c1) -> groups (0,1); in {1,3}: groups (2,3).
    float qa0 = 0.f, qa1 = 0.f;   // row r
    float qb0 = 0.f, qb1 = 0.f;   // row r+8
    #pragma unroll
    for (int j = 0; j < 16; ++j) {
        qa0 = fmaf(d[j][0], d[j][0], qa0);
        qa1 = fmaf(d[j][1], d[j][1], qa1);
        qb0 = fmaf(d[j][2], d[j][2], qb0);
        qb1 = fmaf(d[j][3], d[j][3], qb1);
    }
    // Combine same-group lanes (lane ^ 2 has same lane&1).
    qa0 += __shfl_xor_sync(0xffffffffu, qa0, 2);
    qa1 += __shfl_xor_sync(0xffffffffu, qa1, 2);
    qb0 += __shfl_xor_sync(0xffffffffu, qb0, 2);
    qb1 += __shfl_xor_sync(0xffffffffu, qb1, 2);
    // Fetch the complementary group pair from lane ^ 1.
    const float ra0 = __shfl_xor_sync(0xffffffffu, qa0, 1);
    const float ra1 = __shfl_xor_sync(0xffffffffu, qa1, 1);
    const float rb0 = __shfl_xor_sync(0xffffffffu, qb0, 1);
    const float rb1 = __shfl_xor_sync(0xffffffffu, qb1, 1);

    if ((lane & 3) == 0) {
        const int row0 = blockIdx.x * TCA_ROWS + R0 + (lane >> 2);
        // row r: q = {qa0, qa1, ra0, ra1}; row r+8: {qb0, qb1, rb0, rb1}
        #pragma unroll
        for (int h = 0; h < 2; ++h) {
            const float q0 = h ? qb0 : qa0;
            const float q1 = h ? qb1 : qa1;
            const float q2 = h ? rb0 : ra0;
            const float q3 = h ? rb1 : ra1;
            const float S = q0 + q1 + q2 + q3;   // == ||x||^2 (U orthogonal)
            const float inv_s = 1.0f / S;
            const float p0 = q0 * inv_s, p1 = q1 * inv_s;
            const float p2 = q2 * inv_s, p3 = q3 * inv_s;
            const float mx = fmaxf(fmaxf(p0, p1), fmaxf(p2, p3));
            const float e0 = expf(p0 - mx), e1 = expf(p1 - mx);
            const float e2 = expf(p2 - mx), e3 = expf(p3 - mx);
            const float inv = 1.0f / (e0 + e1 + e2 + e3);
            reinterpret_cast<float4*>(out)[row0 + h * 8] =
                make_float4(e0 * inv, e1 * inv, e2 * inv, e3 * inv);
        }
    }
}

// ----------------------------- launch --------------------------------
extern "C" void kernel_launch(void* const* d_in, const int* in_sizes, int n_in,
                              void* d_out, int out_size) {
    const float* x   = (const float*)d_in[0];
    const float* QC1 = (const float*)d_in[1];
    const float* QC2 = (const float*)d_in[2];
    const float* QC3 = (const float*)d_in[3];
    const float* QP1 = (const float*)d_in[4];
    const float* QP2 = (const float*)d_in[5];
    const float* QP3 = (const float*)d_in[6];
    const float* QF  = (const float*)d_in[7];

    const int B = in_sizes[0] / 128;

    build_U_kernel<<<16, 256>>>(QC1, QC2, QC3, QP1, QP2, QP3, QF);

    cudaFuncSetAttribute(qcnn_mma_kernel,
                         cudaFuncAttributeMaxDynamicSharedMemorySize,
                         SM_TC_TOTAL);
    qcnn_mma_kernel<<<B / TCA_ROWS, TCA_THREADS, SM_TC_TOTAL>>>(
        x, (float*)d_out);
}

// round 11
// speedup vs baseline: 1.2581x; 1.2581x over previous
#include <cuda_runtime.h>
#include <cuda_bf16.h>
#include <cstdint>

// =====================================================================
// ATQCNN factorization:
//   U = fixed 128x128 orthogonal circuit matrix (wires 0..6; 7,8 inert)
//   Y[b] = U x[b];  q[b,k] = sum_{m&3==k} Y[b,m]^2;  out = softmax(q/sum q)
// Kernel 1: warp-per-basis register simulation -> U as bf16 split
//           (U = U_hi + U_lo residual; 3-pass product err ~4e-7 measured).
// Kernel 2: mma.sync (m16n8k16 bf16) GEMM, 3 accumulated passes
//           (Xhi·Uhi + Xlo·Uhi + Xhi·Ulo). 128 CTAs x 4 warps
//           (2m x 2n split), B fragments shared across hi/lo passes,
//           cross-warp q-combine via smem, softmax epilogue.
// =====================================================================

__device__ __align__(16) __nv_bfloat16 g_Uhi[128 * 128];  // [m][i] row-major
__device__ __align__(16) __nv_bfloat16 g_Ulo[128 * 128];  // [m][i] row-major

// --------------------- warp-MMA helpers -------------------------------
__device__ __forceinline__ uint32_t smem_to_u32(const void* p) {
    uint32_t a;
    asm("{ .reg .u64 t; cvta.to.shared.u64 t, %1; cvt.u32.u64 %0, t; }"
        : "=r"(a) : "l"(p));
    return a;
}
__device__ __forceinline__ void ldsm4(uint32_t& r0, uint32_t& r1,
                                      uint32_t& r2, uint32_t& r3, uint32_t a) {
    asm volatile("ldmatrix.sync.aligned.m8n8.x4.shared.b16 {%0,%1,%2,%3}, [%4];"
                 : "=r"(r0), "=r"(r1), "=r"(r2), "=r"(r3) : "r"(a));
}
__device__ __forceinline__ void ldsm2(uint32_t& r0, uint32_t& r1, uint32_t a) {
    asm volatile("ldmatrix.sync.aligned.m8n8.x2.shared.b16 {%0,%1}, [%2];"
                 : "=r"(r0), "=r"(r1) : "r"(a));
}
__device__ __forceinline__ void mma_bf16(float* d, const uint32_t* a,
                                         uint32_t b0, uint32_t b1) {
    asm volatile(
        "mma.sync.aligned.m16n8k16.row.col.f32.bf16.bf16.f32 "
        "{%0,%1,%2,%3}, {%4,%5,%6,%7}, {%8,%9}, {%0,%1,%2,%3};"
        : "+f"(d[0]), "+f"(d[1]), "+f"(d[2]), "+f"(d[3])
        : "r"(a[0]), "r"(a[1]), "r"(a[2]), "r"(a[3]), "r"(b0), "r"(b1));
}
__device__ __forceinline__ uint32_t pack_bf2(__nv_bfloat16 a, __nv_bfloat16 b) {
    __nv_bfloat162 t = __halves2bfloat162(a, b);
    return *reinterpret_cast<uint32_t*>(&t);
}

// --------------------- gate primitives (register sim) -----------------
template<int P>
__device__ __forceinline__ void ry_p(float a[4], float c, float s, int lane) {
    if constexpr (P == 0) {
        float n0 = c * a[0] - s * a[1];
        float n1 = fmaf(s, a[0], c * a[1]);
        float n2 = c * a[2] - s * a[3];
        float n3 = fmaf(s, a[2], c * a[3]);
        a[0] = n0; a[1] = n1; a[2] = n2; a[3] = n3;
    } else if constexpr (P == 1) {
        float n0 = c * a[0] - s * a[2];
        float n2 = fmaf(s, a[0], c * a[2]);
        float n1 = c * a[1] - s * a[3];
        float n3 = fmaf(s, a[1], c * a[3]);
        a[0] = n0; a[1] = n1; a[2] = n2; a[3] = n3;
    } else {
        constexpr int M = 1 << (P - 2);
        const float sgn = (lane & M) ? s : -s;
        #pragma unroll
        for (int r = 0; r < 4; ++r) {
            float pr = __shfl_xor_sync(0xffffffffu, a[r], M);
            a[r] = fmaf(sgn, pr, c * a[r]);
        }
    }
}
template<int W>
__device__ __forceinline__ void ry_w(float a[4], float2 cs, int lane) {
    ry_p<6 - W>(a, cs.x, cs.y, lane);
}
template<int PC, int PT>
__device__ __forceinline__ void cnot_p(float a[4], int lane) {
    if constexpr (PT >= 2) {
        constexpr int MT = 1 << (PT - 2);
        if constexpr (PC >= 2) {
            constexpr int MC = 1 << (PC - 2);
            const bool ctl = (lane & MC) != 0;
            #pragma unroll
            for (int r = 0; r < 4; ++r) {
                float pr = __shfl_xor_sync(0xffffffffu, a[r], MT);
                a[r] = ctl ? pr : a[r];
            }
        } else {
            #pragma unroll
            for (int r = 0; r < 4; ++r) {
                if ((r >> PC) & 1) {
                    a[r] = __shfl_xor_sync(0xffffffffu, a[r], MT);
                }
            }
        }
    } else {
        if constexpr (PC >= 2) {
            constexpr int MC = 1 << (PC - 2);
            const bool ctl = (lane & MC) != 0;
            if constexpr (PT == 0) {
                float t0 = a[0], t2 = a[2];
                a[0] = ctl ? a[1] : a[0];  a[1] = ctl ? t0 : a[1];
                a[2] = ctl ? a[3] : a[2];  a[3] = ctl ? t2 : a[3];
            } else {
                float t0 = a[0], t1 = a[1];
                a[0] = ctl ? a[2] : a[0];  a[2] = ctl ? t0 : a[2];
                a[1] = ctl ? a[3] : a[1];  a[3] = ctl ? t1 : a[3];
            }
        } else {
            if constexpr (PC == 1 && PT == 0) { float t = a[2]; a[2] = a[3]; a[3] = t; }
            else                              { float t = a[1]; a[1] = a[3]; a[3] = t; }
        }
    }
}
template<int C, int T>
__device__ __forceinline__ void cnot_w(float a[4], int lane) {
    cnot_p<6 - C, 6 - T>(a, lane);
}
template<int WA, int WB>
__device__ __forceinline__ void conv6(float a[4], int lane,
                                      const float2* __restrict__ cs, int base) {
    #pragma unroll
    for (int q = 0; q < 6; ++q) {
        ry_w<WA>(a, cs[base + 2 * q], lane);
        ry_w<WB>(a, cs[base + 2 * q + 1], lane);
        cnot_w<WA, WB>(a, lane);
    }
}

// ----------------------------- Kernel 1 ------------------------------
// 16 blocks x 256 threads; one warp per basis state (= input index i).
__global__ __launch_bounds__(256) void build_U_kernel(
        const float* __restrict__ QC1, const float* __restrict__ QC2,
        const float* __restrict__ QC3, const float* __restrict__ QP1,
        const float* __restrict__ QP2, const float* __restrict__ QP3,
        const float* __restrict__ QF) {
    __shared__ float2 cs[46];
    const int tid  = threadIdx.x;
    const int lane = tid & 31;
    const int basis = blockIdx.x * 8 + (tid >> 5);

    if (tid < 46) {
        float ang;
        if      (tid < 12) ang = QC1[tid];
        else if (tid < 24) ang = QC2[tid - 12];
        else if (tid < 36) ang = QC3[tid - 24];
        else if (tid == 36) ang =  QP1[0];
        else if (tid == 37) ang =  QP1[1];
        else if (tid == 38) ang = -QP1[1];
        else if (tid == 39) ang =  QP2[0];
        else if (tid == 40) ang =  QP2[1];
        else if (tid == 41) ang = -QP2[1];
        else if (tid == 42) ang =  QP3[0];
        else if (tid == 43) ang =  QP3[1];
        else if (tid == 44) ang = -QP3[1];
        else               ang = QF[0] + QF[1] + QF[2] + QF[3];  // RY angles add
        float sn, c;
        sincosf(0.5f * ang, &sn, &c);
        cs[tid] = make_float2(c, sn);
    }
    __syncthreads();

    float a[4];
    #pragma unroll
    for (int r = 0; r < 4; ++r) a[r] = (lane * 4 + r == basis) ? 1.0f : 0.0f;

    conv6<0,1>(a, lane, cs, 0);  conv6<1,2>(a, lane, cs, 0);
    conv6<2,3>(a, lane, cs, 0);  conv6<3,4>(a, lane, cs, 0);
    conv6<4,5>(a, lane, cs, 0);  conv6<5,6>(a, lane, cs, 0);
    conv6<6,0>(a, lane, cs, 0);
    ry_w<0>(a, cs[36], lane); ry_w<3>(a, cs[37], lane);
    cnot_w<0,3>(a, lane);     ry_w<3>(a, cs[38], lane);
    ry_w<1>(a, cs[36], lane); ry_w<4>(a, cs[37], lane);
    cnot_w<1,4>(a, lane);     ry_w<4>(a, cs[38], lane);
    ry_w<2>(a, cs[36], lane); ry_w<5>(a, cs[37], lane);
    cnot_w<2,5>(a, lane);     ry_w<5>(a, cs[38], lane);
    conv6<3,4>(a, lane, cs, 12);
    conv6<4,5>(a, lane, cs, 12);
    conv6<5,6>(a, lane, cs, 12);
    #pragma unroll
    for (int q = 0; q < 6; ++q) {
        ry_w<6>(a, cs[12 + 2 * q], lane);
        ry_w<3>(a, cs[13 + 2 * q], lane);
        cnot_w<6,0>(a, lane);
    }
    ry_w<3>(a, cs[39], lane); ry_w<5>(a, cs[40], lane);
    cnot_w<3,5>(a, lane);     ry_w<5>(a, cs[41], lane);
    ry_w<4>(a, cs[39], lane); ry_w<6>(a, cs[40], lane);
    cnot_w<4,6>(a, lane);     ry_w<6>(a, cs[41], lane);
    #pragma unroll
    for (int q = 0; q < 6; ++q) {
        ry_w<5>(a, cs[24 + 2 * q], lane);
        ry_w<6>(a, cs[25 + 2 * q], lane);
        cnot_w<4,5>(a, lane);
    }
    ry_w<5>(a, cs[42], lane); ry_w<6>(a, cs[43], lane);
    cnot_w<4,6>(a, lane);     ry_w<6>(a, cs[44], lane);
    ry_w<5>(a, cs[45], lane);
    cnot_w<5,6>(a, lane);
    cnot_w<6,5>(a, lane);

    // a[r] = U[m = lane*4 + r][i = basis]; split to bf16 hi + residual lo.
    #pragma unroll
    for (int r = 0; r < 4; ++r) {
        const int m = lane * 4 + r;
        const __nv_bfloat16 h = __float2bfloat16(a[r]);
        g_Uhi[m * 128 + basis] = h;
        g_Ulo[m * 128 + basis] = __float2bfloat16(a[r] - __bfloat162float(h));
    }
}

// ----------------------------- Kernel 2 ------------------------------
// 128 blocks x 128 threads (4 warps). Block = 32 batches.
// Warp (mi = w>>1, nj = w&1): rows mi*16..+15, cols nj*64..+63
// = 8 m16n8 accum tiles, K = 128 = 8 k16 steps.
// Passes 0+1 fused (share B=Uhi fragments); pass 2 uses Ulo.
// Cross-warp (nj) q-combine via smem, then softmax + float4 store.

#define TCA_THREADS 128
#define TCA_ROWS 32
#define PITCH 272                                // bytes per tile row
#define SM_XHI 0
#define SM_XLO (TCA_ROWS * PITCH)
#define SM_UHI (2 * TCA_ROWS * PITCH)
#define SM_ULO (2 * TCA_ROWS * PITCH + 128 * PITCH)
#define SM_RED (2 * TCA_ROWS * PITCH + 2 * 128 * PITCH)
#define SM_TC_TOTAL (SM_RED + 2 * TCA_ROWS * 16)   // + [2][32] float4

__global__ __launch_bounds__(TCA_THREADS) void qcnn_mma_kernel(
        const float* __restrict__ X, float* __restrict__ out) {
    extern __shared__ char smem[];
    const uint32_t smem_base = smem_to_u32(smem);
    float4* Red = reinterpret_cast<float4*>(smem + SM_RED);  // [nj][32]
    const int tid  = threadIdx.x;
    const int warp = tid >> 5;
    const int lane = tid & 31;

    // --- Stage X tile (32 rows) as bf16 hi/lo into padded smem ---
    const float4* gX4 =
        reinterpret_cast<const float4*>(X + (size_t)blockIdx.x * TCA_ROWS * 128);
    #pragma unroll
    for (int it = 0; it < 8; ++it) {
        const int idx = tid + it * TCA_THREADS;   // 1024 float4 chunks
        const float4 v = gX4[idx];
        const int row = idx >> 5;
        const int col = (idx & 31) << 2;
        const __nv_bfloat16 h0 = __float2bfloat16(v.x);
        const __nv_bfloat16 h1 = __float2bfloat16(v.y);
        const __nv_bfloat16 h2 = __float2bfloat16(v.z);
        const __nv_bfloat16 h3 = __float2bfloat16(v.w);
        const __nv_bfloat16 l0 = __float2bfloat16(v.x - __bfloat162float(h0));
        const __nv_bfloat16 l1 = __float2bfloat16(v.y - __bfloat162float(h1));
        const __nv_bfloat16 l2 = __float2bfloat16(v.z - __bfloat162float(h2));
        const __nv_bfloat16 l3 = __float2bfloat16(v.w - __bfloat162float(h3));
        const int off = row * PITCH + col * 2;
        *reinterpret_cast<uint2*>(smem + SM_XHI + off) =
            make_uint2(pack_bf2(h0, h1), pack_bf2(h2, h3));
        *reinterpret_cast<uint2*>(smem + SM_XLO + off) =
            make_uint2(pack_bf2(l0, l1), pack_bf2(l2, l3));
    }
    // --- Stage U hi/lo (128 rows) with uint4 loads ---
    const uint4* gUh = reinterpret_cast<const uint4*>(g_Uhi);  // 8 bf16/uint4
    const uint4* gUl = reinterpret_cast<const uint4*>(g_Ulo);
    #pragma unroll
    for (int it = 0; it < 16; ++it) {
        const int idx = tid + it * TCA_THREADS;   // 2048 uint4 chunks
        const int row = idx >> 4;
        const int c16 = (idx & 15) * 16;          // byte offset within row
        const int off = row * PITCH + c16;
        *reinterpret_cast<uint4*>(smem + SM_UHI + off) = gUh[idx];
        *reinterpret_cast<uint4*>(smem + SM_ULO + off) = gUl[idx];
    }
    __syncthreads();

    // --- MMA mainloop ---
    const int mi = warp >> 1;                     // row tile 0..1
    const int nj = warp & 1;                      // col half 0..1
    const int R0 = mi * 16;
    const int C0 = nj * 64;

    float d[8][4];
    #pragma unroll
    for (int j = 0; j < 8; ++j)
        { d[j][0] = 0.f; d[j][1] = 0.f; d[j][2] = 0.f; d[j][3] = 0.f; }

    const uint32_t aHi = smem_base + SM_XHI
        + (uint32_t)(R0 + (lane & 15)) * PITCH + (uint32_t)(lane >> 4) * 16;
    const uint32_t aLo = smem_base + SM_XLO
        + (uint32_t)(R0 + (lane & 15)) * PITCH + (uint32_t)(lane >> 4) * 16;
    const uint32_t bHi = smem_base + SM_UHI
        + (uint32_t)(C0 + (lane & 7)) * PITCH + (uint32_t)((lane >> 3) & 1) * 16;
    const uint32_t bLo = smem_base + SM_ULO
        + (uint32_t)(C0 + (lane & 7)) * PITCH + (uint32_t)((lane >> 3) & 1) * 16;

    // Fused passes 0+1: Xhi*Uhi + Xlo*Uhi (B fragments loaded once).
    #pragma unroll 1
    for (int ks = 0; ks < 8; ++ks) {
        uint32_t ah[4], al[4];
        ldsm4(ah[0], ah[1], ah[2], ah[3], aHi + ks * 32);
        ldsm4(al[0], al[1], al[2], al[3], aLo + ks * 32);
        const uint32_t bks = bHi + ks * 32;
        #pragma unroll
        for (int j = 0; j < 8; ++j) {
            uint32_t b0, b1;
            ldsm2(b0, b1, bks + j * (8 * PITCH));
            mma_bf16(d[j], ah, b0, b1);
            mma_bf16(d[j], al, b0, b1);
        }
    }
    // Pass 2: Xhi*Ulo.
    #pragma unroll 1
    for (int ks = 0; ks < 8; ++ks) {
        uint32_t ah[4];
        ldsm4(ah[0], ah[1], ah[2], ah[3], aHi + ks * 32);
        const uint32_t bks = bLo + ks * 32;
        #pragma unroll
        for (int j = 0; j < 8; ++j) {
            uint32_t b0, b1;
            ldsm2(b0, b1, bks + j * (8 * PITCH));
            mma_bf16(d[j], ah, b0, b1);
        }
    }

    // --- In-warp q reduction (fragment cols: group parity by lane&1) ---
    float qa0 = 0.f, qa1 = 0.f;   // row r = lane>>2
    float qb0 = 0.f, qb1 = 0.f;   // row r+8
    #pragma unroll
    for (int j = 0; j < 8; ++j) {
        qa0 = fmaf(d[j][0], d[j][0], qa0);
        qa1 = fmaf(d[j][1], d[j][1], qa1);
        qb0 = fmaf(d[j][2], d[j][2], qb0);
        qb1 = fmaf(d[j][3], d[j][3], qb1);
    }
    qa0 += __shfl_xor_sync(0xffffffffu, qa0, 2);
    qa1 += __shfl_xor_sync(0xffffffffu, qa1, 2);
    qb0 += __shfl_xor_sync(0xffffffffu, qb0, 2);
    qb1 += __shfl_xor_sync(0xffffffffu, qb1, 2);
    const float ra0 = __shfl_xor_sync(0xffffffffu, qa0, 1);
    const float ra1 = __shfl_xor_sync(0xffffffffu, qa1, 1);
    const float rb0 = __shfl_xor_sync(0xffffffffu, qb0, 1);
    const float rb1 = __shfl_xor_sync(0xffffffffu, qb1, 1);

    if ((lane & 3) == 0) {
        const int r = lane >> 2;                  // 0..7
        Red[nj * 32 + R0 + r]     = make_float4(qa0, qa1, ra0, ra1);
        Red[nj * 32 + R0 + r + 8] = make_float4(qb0, qb1, rb0, rb1);
    }
    __syncthreads();

    // --- Final combine + softmax: thread t < 32 owns batch row t ---
    if (tid < TCA_ROWS) {
        const float4 u = Red[tid];
        const float4 v = Red[32 + tid];
        const float q0 = u.x + v.x, q1 = u.y + v.y;
        const float q2 = u.z + v.z, q3 = u.w + v.w;
        const float S = q0 + q1 + q2 + q3;        // == ||x||^2 (U orthogonal)
        const float inv_s = 1.0f / S;
        const float p0 = q0 * inv_s, p1 = q1 * inv_s;
        const float p2 = q2 * inv_s, p3 = q3 * inv_s;
        const float mx = fmaxf(fmaxf(p0, p1), fmaxf(p2, p3));
        const float e0 = expf(p0 - mx), e1 = expf(p1 - mx);
        const float e2 = expf(p2 - mx), e3 = expf(p3 - mx);
        const float inv = 1.0f / (e0 + e1 + e2 + e3);
        reinterpret_cast<float4*>(out)[blockIdx.x * TCA_ROWS + tid] =
            make_float4(e0 * inv, e1 * inv, e2 * inv, e3 * inv);
    }
}

// ----------------------------- launch --------------------------------
extern "C" void kernel_launch(void* const* d_in, const int* in_sizes, int n_in,
                              void* d_out, int out_size) {
    const float* x   = (const float*)d_in[0];
    const float* QC1 = (const float*)d_in[1];
    const float* QC2 = (const float*)d_in[2];
    const float* QC3 = (const float*)d_in[3];
    const float* QP1 = (const float*)d_in[4];
    const float* QP2 = (const float*)d_in[5];
    const float* QP3 = (const float*)d_in[6];
    const float* QF  = (const float*)d_in[7];

    const int B = in_sizes[0] / 128;

    build_U_kernel<<<16, 256>>>(QC1, QC2, QC3, QP1, QP2, QP3, QF);

    cudaFuncSetAttribute(qcnn_mma_kernel,
                         cudaFuncAttributeMaxDynamicSharedMemorySize,
                         SM_TC_TOTAL);
    qcnn_mma_kernel<<<B / TCA_ROWS, TCA_THREADS, SM_TC_TOTAL>>>(
        x, (float*)d_out);
}